// round 14
// baseline (speedup 1.0000x reference)
#include <cuda_runtime.h>
#include <cuda_fp16.h>
#include <cstdint>

#define NB 4
#define NL 4096
#define DMODEL 1024
#define DINNER 2048
#define NHEADS 32
#define HEADDIM 64
#define DSTATE 64
#define NCHUNK 64
#define CHUNKL 64
#define CONVDIM 2176
#define DINPROJ 4256
#define NROWS (NB*NL)

// ---------------- scratch (device globals; no allocations allowed) ----------
__device__ __align__(16) float g_z[(size_t)NROWS * DINNER];
__device__ __align__(16) float g_xraw[(size_t)NROWS * CONVDIM];
__device__ __align__(16) float g_xbc[(size_t)NROWS * CONVDIM];
__device__ __align__(16) float g_dt[(size_t)NROWS * NHEADS];
__device__ __align__(16) float g_y[(size_t)NROWS * DINNER];
__device__ __align__(16) float g_states[(size_t)NB * NCHUNK * NHEADS * HEADDIM * DSTATE];
__device__ __align__(16) float g_cumsum[(size_t)NB * NHEADS * NCHUNK * CHUNKL];
__device__ __align__(16) float g_cbt[(size_t)NB * NCHUNK * CHUNKL * CHUNKL];

// fp16 operands
__device__ __align__(16) __half g_uh[(size_t)NROWS * DMODEL];
__device__ __align__(16) __half g_wih[(size_t)DINPROJ * DMODEL];
__device__ __align__(16) __half g_wil[(size_t)DINPROJ * DMODEL];
__device__ __align__(16) __half g_woh[(size_t)DMODEL * DINNER];
__device__ __align__(16) __half g_yh[(size_t)NROWS * DINNER];

__device__ __forceinline__ float softplusf(float x) {
    return (x > 20.f) ? x : log1pf(__expf(x));
}
__device__ __forceinline__ float siluf(float x) {
    return __fdividef(x, 1.f + __expf(-x));
}
__device__ __forceinline__ void splith(float v, __half& h, __half& l) {
    h = __float2half_rn(v);
    l = __float2half_rn(v - __half2float(h));
}
__device__ __forceinline__ uint32_t smem_u32(const void* p) {
    uint32_t a;
    asm("{ .reg .u64 t; cvta.to.shared.u64 t, %1; cvt.u32.u64 %0, t; }" : "=r"(a) : "l"(p));
    return a;
}
__device__ __forceinline__ void cpasync16(uint32_t dst, const void* src, uint32_t srcsz) {
    asm volatile("cp.async.cg.shared.global [%0], [%1], 16, %2;"
                 :: "r"(dst), "l"(src), "r"(srcsz) : "memory");
}
#define CP_COMMIT() asm volatile("cp.async.commit_group;" ::: "memory")
#define CP_WAIT1()  asm volatile("cp.async.wait_group 1;" ::: "memory")

__device__ __forceinline__ void ldmat4(uint32_t* r, uint32_t addr) {
    asm volatile("ldmatrix.sync.aligned.m8n8.x4.shared.b16 {%0,%1,%2,%3}, [%4];"
                 : "=r"(r[0]), "=r"(r[1]), "=r"(r[2]), "=r"(r[3]) : "r"(addr));
}
#define MMA_F16(d, a, b) \
    asm volatile("mma.sync.aligned.m16n8k16.row.col.f32.f16.f16.f32 " \
                 "{%0,%1,%2,%3}, {%4,%5,%6,%7}, {%8,%9}, {%0,%1,%2,%3};" \
                 : "+f"((d)[0]), "+f"((d)[1]), "+f"((d)[2]), "+f"((d)[3]) \
                 : "r"((a)[0]), "r"((a)[1]), "r"((a)[2]), "r"((a)[3]), \
                   "r"((b)[0]), "r"((b)[1]))

// ---------------- fp32 -> fp16 conversion preps -----------------------------
__global__ void __launch_bounds__(256) cvt_kernel(
    const float* __restrict__ src, __half* __restrict__ dst, int n4)
{
    int idx = blockIdx.x * 256 + threadIdx.x;
    if (idx >= n4) return;
    float4 v = ((const float4*)src)[idx];
    __half h[4] = {__float2half_rn(v.x), __float2half_rn(v.y),
                   __float2half_rn(v.z), __float2half_rn(v.w)};
    ((uint2*)dst)[idx] = *(uint2*)h;
}
__global__ void __launch_bounds__(256) split_kernel(
    const float* __restrict__ src, __half* __restrict__ hi,
    __half* __restrict__ lo, int n4)
{
    int idx = blockIdx.x * 256 + threadIdx.x;
    if (idx >= n4) return;
    float4 v = ((const float4*)src)[idx];
    __half h[4], l[4];
    splith(v.x, h[0], l[0]); splith(v.y, h[1], l[1]);
    splith(v.z, h[2], l[2]); splith(v.w, h[3], l[3]);
    ((uint2*)hi)[idx] = *(uint2*)h;
    ((uint2*)lo)[idx] = *(uint2*)l;
}

// ========== fp16 mma.sync GEMM: C = A @ W^T ==========
#define GST 72
#define GROWB (GST * 2)
#define GTILE (128 * GST * 2)
#define GSTAGE (3 * GTILE)
#define GSMEM (2 * GSTAGE)
template <int MODE, int TERMS>
__global__ void __launch_bounds__(256) mma_gemm(
    const __half* __restrict__ Ap, const __half* __restrict__ Whi,
    const __half* __restrict__ Wlo,
    float* __restrict__ Cp, int N_, int K_, const float* __restrict__ dt_bias)
{
    extern __shared__ char smem[];
    const uint32_t sbase = smem_u32(smem);
    const int tid = threadIdx.x;
    const int row0 = blockIdx.y * 128;
    const int col0 = blockIdx.x * 128;
    const __half* A = (MODE == 0) ? Ap : g_yh;

    const int wid = tid >> 5, lane = tid & 31;
    const int wm = wid >> 2, wn = wid & 3;

    float acc[4][4][4];
#pragma unroll
    for (int i = 0; i < 4; i++)
#pragma unroll
        for (int j = 0; j < 4; j++)
#pragma unroll
            for (int q = 0; q < 4; q++) acc[i][j][q] = 0.f;

    const int iters = K_ >> 6;

    auto load_stage = [&](int st, int buf) {
        const int k0 = st << 6;
        const uint32_t sb = sbase + buf * GSTAGE;
#pragma unroll
        for (int p = 0; p < 4; p++) {
            int chunk = tid + p * 256;
            int row = chunk >> 3, c8 = chunk & 7;
            uint32_t doff = (uint32_t)(row * GROWB + c8 * 16);
            size_t aoff = (size_t)(row0 + row) * K_ + k0 + c8 * 8;
            cpasync16(sb + doff, A + aoff, 16u);
            int wr = col0 + row;
            uint32_t wsz = (wr < N_) ? 16u : 0u;
            size_t woff = (size_t)wr * K_ + k0 + c8 * 8;
            cpasync16(sb + GTILE + doff, Whi + woff, wsz);
            if (TERMS == 2)
                cpasync16(sb + 2 * GTILE + doff, Wlo + woff, wsz);
        }
        CP_COMMIT();
    };

    load_stage(0, 0);
    load_stage(1, 1);

    const uint32_t aoffb = (uint32_t)((lane & 15) * GROWB + ((lane >> 4) & 1) * 16);
    const uint32_t boffb = (uint32_t)(((lane & 7) + ((lane >> 4) << 3)) * GROWB + ((lane >> 3) & 1) * 16);

    for (int it = 0; it < iters; it++) {
        CP_WAIT1();
        __syncthreads();
        const uint32_t sb = sbase + (it & 1) * GSTAGE;
        const uint32_t sAh = sb, sWh = sb + GTILE, sWl = sb + 2 * GTILE;

#pragma unroll
        for (int ks = 0; ks < 4; ks++) {
            uint32_t bh[8], bl[8];
#pragma unroll
            for (int jj = 0; jj < 2; jj++) {
                uint32_t rb = (uint32_t)((wn * 32 + jj * 16) * GROWB) + boffb + ks * 32;
                ldmat4(&bh[jj * 4], sWh + rb);
                if (TERMS == 2) ldmat4(&bl[jj * 4], sWl + rb);
            }
#pragma unroll
            for (int i = 0; i < 4; i++) {
                uint32_t ra = (uint32_t)((wm * 64 + i * 16) * GROWB) + aoffb + ks * 32;
                uint32_t ah[4];
                ldmat4(ah, sAh + ra);
#pragma unroll
                for (int j = 0; j < 4; j++)
                    MMA_F16(acc[i][j], ah, &bh[(j >> 1) * 4 + (j & 1) * 2]);
                if (TERMS == 2) {
#pragma unroll
                    for (int j = 0; j < 4; j++)
                        MMA_F16(acc[i][j], ah, &bl[(j >> 1) * 4 + (j & 1) * 2]);
                }
            }
        }
        __syncthreads();
        if (it + 2 < iters) load_stage(it + 2, it & 1);
    }

#pragma unroll
    for (int i = 0; i < 4; i++) {
        const int rb = row0 + wm * 64 + i * 16 + (lane >> 2);
#pragma unroll
        for (int j = 0; j < 4; j++) {
            const int c = col0 + wn * 32 + j * 8 + (lane & 3) * 2;
#pragma unroll
            for (int half = 0; half < 2; half++) {
                const int r = rb + half * 8;
                const float v0 = acc[i][j][half * 2];
                const float v1 = acc[i][j][half * 2 + 1];
                if (MODE == 0) {
                    if (c < DINNER) {
                        *(float2*)&g_z[(size_t)r * DINNER + c] = make_float2(v0, v1);
                    } else if (c < DINNER + CONVDIM) {
                        *(float2*)&g_xraw[(size_t)r * CONVDIM + (c - DINNER)] = make_float2(v0, v1);
                    } else if (c < DINPROJ) {
                        int h = c - (DINNER + CONVDIM);
                        g_dt[(size_t)r * NHEADS + h] = softplusf(v0 + dt_bias[h]);
                        g_dt[(size_t)r * NHEADS + h + 1] = softplusf(v1 + dt_bias[h + 1]);
                    }
                } else {
                    *(float2*)&Cp[(size_t)r * N_ + c] = make_float2(v0, v1);
                }
            }
        }
    }
}

// -------- depthwise conv (k=4, causal) + silu, 4 rows per thread -----------
__global__ void __launch_bounds__(256) conv_kernel(
    const float* __restrict__ conv_w, const float* __restrict__ conv_b)
{
    const int CV4 = CONVDIM / 4;
    size_t idx = (size_t)blockIdx.x * blockDim.x + threadIdx.x;
    if (idx >= (size_t)(NROWS / 4) * CV4) return;
    int chv = (int)(idx % CV4);
    int blg = (int)(idx / CV4);
    int l0 = (blg % (NL / 4)) * 4;
    int b  = blg / (NL / 4);
    int ch = chv * 4;

    float4 x[7];
#pragma unroll
    for (int k = 0; k < 7; k++) {
        int ls = l0 - 3 + k;
        x[k] = (ls >= 0)
            ? *(const float4*)&g_xraw[((size_t)b * NL + ls) * CONVDIM + ch]
            : make_float4(0.f, 0.f, 0.f, 0.f);
    }
    float w[4][4], bia[4];
#pragma unroll
    for (int i = 0; i < 4; i++) {
        bia[i] = conv_b[ch + i];
#pragma unroll
        for (int k = 0; k < 4; k++) w[i][k] = conv_w[(ch + i) * 4 + k];
    }
#pragma unroll
    for (int r = 0; r < 4; r++) {
        float a0 = bia[0], a1 = bia[1], a2 = bia[2], a3 = bia[3];
#pragma unroll
        for (int k = 0; k < 4; k++) {
            const float4 xv = x[r + k];
            a0 = fmaf(xv.x, w[0][k], a0);
            a1 = fmaf(xv.y, w[1][k], a1);
            a2 = fmaf(xv.z, w[2][k], a2);
            a3 = fmaf(xv.w, w[3][k], a3);
        }
        float4 o;
        o.x = siluf(a0); o.y = siluf(a1); o.z = siluf(a2); o.w = siluf(a3);
        *(float4*)&g_xbc[((size_t)b * NL + l0 + r) * CONVDIM + ch] = o;
    }
}

// ---------------- CBT = C @ B^T per (b,chunk), shared across heads ----------
__global__ void __launch_bounds__(256) cbt_kernel()
{
    __shared__ float Bs[64 * 65];
    __shared__ float Cs[64 * 65];
    const int bc = blockIdx.x;
    const int t = threadIdx.x;

    for (int idx = t; idx < 64 * 16; idx += 256) {
        int l = idx >> 4;
        int n4 = (idx & 15) * 4;
        size_t base = ((size_t)bc * CHUNKL + l) * CONVDIM;
        float4 bv = *(const float4*)&g_xbc[base + DINNER + n4];
        float4 cv = *(const float4*)&g_xbc[base + DINNER + 64 + n4];
        Bs[l * 65 + n4 + 0] = bv.x; Bs[l * 65 + n4 + 1] = bv.y;
        Bs[l * 65 + n4 + 2] = bv.z; Bs[l * 65 + n4 + 3] = bv.w;
        Cs[l * 65 + n4 + 0] = cv.x; Cs[l * 65 + n4 + 1] = cv.y;
        Cs[l * 65 + n4 + 2] = cv.z; Cs[l * 65 + n4 + 3] = cv.w;
    }
    __syncthreads();

    const int r0 = (t >> 4) * 4;
    const int c0 = (t & 15) * 4;
    float ga[4][4];
#pragma unroll
    for (int i = 0; i < 4; i++)
#pragma unroll
        for (int j = 0; j < 4; j++) ga[i][j] = 0.f;
    for (int n = 0; n < 64; n++) {
        float cr[4], br[4];
#pragma unroll
        for (int i = 0; i < 4; i++) cr[i] = Cs[(r0 + i) * 65 + n];
#pragma unroll
        for (int j = 0; j < 4; j++) br[j] = Bs[(c0 + j) * 65 + n];
#pragma unroll
        for (int i = 0; i < 4; i++)
#pragma unroll
            for (int j = 0; j < 4; j++) ga[i][j] = fmaf(cr[i], br[j], ga[i][j]);
    }
    float* dst = g_cbt + (size_t)bc * 4096;
#pragma unroll
    for (int i = 0; i < 4; i++)
#pragma unroll
        for (int j = 0; j < 4; j++)
            dst[(r0 + i) * 64 + c0 + j] = ga[i][j];
}

// ======== chunk: tensor-core state + Y_diag (fp16 2-term mma.sync) ==========
// Split loop remapped: thread owns transposed-row q and 4 consecutive l.
// X/B stores become vectorized uint2 at ~2-way conflict (vs 8-way scalar).
#define CST 72
#define CROWB (CST * 2)
#define TILE_B (64 * CST * 2)
#define CHUNK_DSMEM (5 * TILE_B + 3 * 64 * 4)
__global__ void __launch_bounds__(256) chunk_kernel(const float* __restrict__ A_log)
{
    extern __shared__ __align__(16) char sm[];
    __half* Gh = (__half*)sm;
    __half* Xh = Gh + 64 * CST;
    __half* Xl = Xh + 64 * CST;
    __half* Bh = Xl + 64 * CST;
    __half* Bl = Bh + 64 * CST;
    float* cum = (float*)(Bl + 64 * CST);
    float* dts = cum + 64;
    float* dec = dts + 64;
    const uint32_t sb = smem_u32(sm);
    const uint32_t sGh = sb, sXh = sGh + TILE_B, sXl = sXh + TILE_B,
                   sBh = sXl + TILE_B, sBl = sBh + TILE_B;

    const int blk = blockIdx.x;
    const int h = blk & (NHEADS - 1);
    const int c = (blk / NHEADS) & (NCHUNK - 1);
    const int b = blk / (NHEADS * NCHUNK);
    const int t = threadIdx.x;
    const int wid = t >> 5, lane = t & 31;

    const float Ah_ = -__expf(A_log[h]);

    if (t < 64) {
        float d = g_dt[((size_t)(b * NL + c * CHUNKL + t)) * NHEADS + h];
        dts[t] = d;
        cum[t] = Ah_ * d;
    }
    __syncthreads();
    if (t == 0) {
        float s = 0.f;
        for (int l = 0; l < 64; l++) { s += cum[l]; cum[l] = s; }
    }
    __syncthreads();
    if (t < 64) {
        dec[t] = __expf(cum[63] - cum[t]);
        g_cumsum[(((size_t)(b * NHEADS + h)) * NCHUNK + c) * CHUNKL + t] = cum[t];
    }
    __syncthreads();

    // split phase (transposed thread mapping)
    const float* cbt = g_cbt + ((size_t)(b * NCHUNK + c)) * 4096;
    for (int idx = t; idx < 64 * 16; idx += 256) {
        int q  = idx & 63;           // transposed-row (p for X, n for B, s for G)
        int l0 = (idx >> 6) * 4;     // 4 consecutive l per thread
        __half xh4[4], xl4[4], bh4[4], bl4v[4];
        float cq = cum[q];
#pragma unroll
        for (int i = 0; i < 4; i++) {
            int l = l0 + i;
            size_t rbase = ((size_t)(b * NL + c * CHUNKL + l)) * CONVDIM;
            float xv = g_xbc[rbase + h * HEADDIM + q];
            float bv = g_xbc[rbase + DINNER + q];
            float gv = cbt[l * 64 + q];
            splith(xv * dts[l], xh4[i], xl4[i]);
            splith(bv * dec[l], bh4[i], bl4v[i]);
            float gm = (l >= q) ? gv * __expf(cum[l] - cq) : 0.f;
            Gh[l * CST + q] = __float2half_rn(gm);
        }
        *(uint2*)&Xh[q * CST + l0] = *(uint2*)xh4;
        *(uint2*)&Xl[q * CST + l0] = *(uint2*)xl4;
        *(uint2*)&Bh[q * CST + l0] = *(uint2*)bh4;
        *(uint2*)&Bl[q * CST + l0] = *(uint2*)bl4v;
    }
    __syncthreads();

    const int rows0 = (wid & 3) * 16;
    const uint32_t aoffb = (uint32_t)((lane & 15) * CROWB + ((lane >> 4) & 1) * 16);
    const uint32_t boffb = (uint32_t)(((lane & 7) + ((lane >> 4) << 3)) * CROWB + ((lane >> 3) & 1) * 16);

    const uint32_t sA_h = (wid < 4) ? sXh : sGh;
    const uint32_t sB_h = (wid < 4) ? sBh : sXh;
    const uint32_t sB_l = (wid < 4) ? sBl : sXl;

    float acc[8][4];
#pragma unroll
    for (int j = 0; j < 8; j++)
#pragma unroll
        for (int q = 0; q < 4; q++) acc[j][q] = 0.f;

#pragma unroll
    for (int kt = 0; kt < 4; kt++) {
        uint32_t ah[4];
        ldmat4(ah, sA_h + rows0 * CROWB + aoffb + kt * 32);
#pragma unroll
        for (int jj = 0; jj < 4; jj++) {
            uint32_t bh[4], bl4[4];
            uint32_t rb = (uint32_t)(jj * 16 * CROWB) + boffb + kt * 32;
            ldmat4(bh, sB_h + rb);
            ldmat4(bl4, sB_l + rb);
            MMA_F16(acc[jj * 2],     ah, &bh[0]);
            MMA_F16(acc[jj * 2 + 1], ah, &bh[2]);
            MMA_F16(acc[jj * 2],     ah, &bl4[0]);
            MMA_F16(acc[jj * 2 + 1], ah, &bl4[2]);
        }
    }

    if (wid < 4) {
        size_t sbout = (size_t)blk * (HEADDIM * DSTATE);
#pragma unroll
        for (int j = 0; j < 8; j++) {
            int n = j * 8 + (lane & 3) * 2;
            int p = rows0 + (lane >> 2);
            *(float2*)&g_states[sbout + (size_t)p * DSTATE + n] = make_float2(acc[j][0], acc[j][1]);
            *(float2*)&g_states[sbout + (size_t)(p + 8) * DSTATE + n] = make_float2(acc[j][2], acc[j][3]);
        }
    } else {
#pragma unroll
        for (int j = 0; j < 8; j++) {
            int p = j * 8 + (lane & 3) * 2;
#pragma unroll
            for (int half = 0; half < 2; half++) {
                int l = rows0 + (lane >> 2) + half * 8;
                int lg = c * CHUNKL + l;
                *(float2*)&g_y[((size_t)(b * NL + lg)) * DINNER + h * HEADDIM + p] =
                    make_float2(acc[j][half * 2], acc[j][half * 2 + 1]);
            }
        }
    }
}

// ---------------- inter-chunk recurrence: one thread per element ------------
__global__ void __launch_bounds__(256) recur_kernel(const float* __restrict__ init_states)
{
    __shared__ float dcs[64];
    const int t = threadIdx.x;
    const int gid = blockIdx.x * 256 + t;
    const int e = gid & 4095;
    const int bh = gid >> 12;
    const int b = bh >> 5, h = bh & 31;

    if (t < 64)
        dcs[t] = __expf(g_cumsum[((size_t)bh * NCHUNK + t) * CHUNKL + 63]);
    __syncthreads();

    float S = init_states[(size_t)h * 4096 + e];
    float* sp0 = g_states + ((((size_t)b * NCHUNK) * NHEADS + h) << 12) + e;
    const size_t cstride = (size_t)NHEADS << 12;

    float cs = sp0[0];
    for (int c = 0; c < NCHUNK; c++) {
        float* sp = sp0 + (size_t)c * cstride;
        float csn = (c < NCHUNK - 1) ? sp[cstride] : 0.f;
        *sp = S;
        S = fmaf(S, dcs[c], cs);
        cs = csn;
    }
}

// ========= Y_off (tensor-core fp16 2-term): Y += es[l]*(C @ S^T) + x*D ======
__global__ void __launch_bounds__(256) yoff_kernel(const float* __restrict__ Dp)
{
    __shared__ __align__(16) char sm[3 * TILE_B + 64 * 4];
    __half* Ch = (__half*)sm;
    __half* Sh = Ch + 64 * CST;
    __half* Sl = Sh + 64 * CST;
    float* es = (float*)(Sl + 64 * CST);
    const uint32_t sb = smem_u32(sm);
    const uint32_t sCh = sb, sSh = sCh + TILE_B, sSl = sSh + TILE_B;

    const int blk = blockIdx.x;
    const int h = blk & (NHEADS - 1);
    const int c = (blk / NHEADS) & (NCHUNK - 1);
    const int b = blk / (NHEADS * NCHUNK);
    const int t = threadIdx.x;
    const int wid = t >> 5, lane = t & 31;
    const float Dh = Dp[h];

    if (t < 64)
        es[t] = __expf(g_cumsum[(((size_t)(b * NHEADS + h)) * NCHUNK + c) * CHUNKL + t]);

    for (int idx = t; idx < 64 * 16; idx += 256) {
        int r = idx >> 4;
        int q = (idx & 15) * 4;
        size_t base = ((size_t)(b * NL + c * CHUNKL + r)) * CONVDIM;
        float4 cv = *(const float4*)&g_xbc[base + DINNER + 64 + q];
        float4 sv = *(const float4*)&g_states[(size_t)blk * 4096 + r * 64 + q];
        float ca[4] = {cv.x, cv.y, cv.z, cv.w};
        float sa[4] = {sv.x, sv.y, sv.z, sv.w};
#pragma unroll
        for (int i = 0; i < 4; i++) {
            Ch[r * CST + q + i] = __float2half_rn(ca[i]);
            __half hh, ll;
            splith(sa[i], hh, ll);
            Sh[r * CST + q + i] = hh; Sl[r * CST + q + i] = ll;
        }
    }
    __syncthreads();

    const int lrow0 = (wid & 3) * 16;
    const int p0 = (wid >> 2) * 32;
    const uint32_t aoffb = (uint32_t)((lane & 15) * CROWB + ((lane >> 4) & 1) * 16);
    const uint32_t boffb = (uint32_t)(((lane & 7) + ((lane >> 4) << 3)) * CROWB + ((lane >> 3) & 1) * 16);

    float acc[4][4];
#pragma unroll
    for (int j = 0; j < 4; j++)
#pragma unroll
        for (int q = 0; q < 4; q++) acc[j][q] = 0.f;

#pragma unroll
    for (int kt = 0; kt < 4; kt++) {
        uint32_t ah[4];
        ldmat4(ah, sCh + lrow0 * CROWB + aoffb + kt * 32);
#pragma unroll
        for (int jj = 0; jj < 2; jj++) {
            uint32_t bh[4], bl4[4];
            uint32_t rb = (uint32_t)((p0 + jj * 16) * CROWB) + boffb + kt * 32;
            ldmat4(bh, sSh + rb);
            ldmat4(bl4, sSl + rb);
            MMA_F16(acc[jj * 2],     ah, &bh[0]);
            MMA_F16(acc[jj * 2 + 1], ah, &bh[2]);
            MMA_F16(acc[jj * 2],     ah, &bl4[0]);
            MMA_F16(acc[jj * 2 + 1], ah, &bl4[2]);
        }
    }

#pragma unroll
    for (int j = 0; j < 4; j++) {
        int p = p0 + j * 8 + (lane & 3) * 2;
#pragma unroll
        for (int half = 0; half < 2; half++) {
            int l = lrow0 + (lane >> 2) + half * 8;
            int lg = c * CHUNKL + l;
            float e = es[l];
            size_t yi = ((size_t)(b * NL + lg)) * DINNER + h * HEADDIM + p;
            float2 yv = *(float2*)&g_y[yi];
            float2 xv = *(float2*)&g_xbc[((size_t)(b * NL + lg)) * CONVDIM + h * HEADDIM + p];
            yv.x = yv.x + e * acc[j][half * 2]     + xv.x * Dh;
            yv.y = yv.y + e * acc[j][half * 2 + 1] + xv.y * Dh;
            *(float2*)&g_y[yi] = yv;
        }
    }
}

// ------- gating (silu(z)) + RMSNorm, emits fp16 hi for out_proj -------------
__global__ void __launch_bounds__(256) norm_kernel(const float* __restrict__ norm_w)
{
    __shared__ float red[8];
    const int row = blockIdx.x;
    const int t = threadIdx.x;
    const int lane = t & 31, wid = t >> 5;
    const float* yr = g_y + (size_t)row * DINNER;
    const float* zr = g_z + (size_t)row * DINNER;

    float vals[8];
    float ss = 0.f;
#pragma unroll
    for (int e = 0; e < 8; e++) {
        int i = e * 256 + t;
        float v = yr[i] * siluf(zr[i]);
        vals[e] = v;
        ss = fmaf(v, v, ss);
    }
#pragma unroll
    for (int o = 16; o > 0; o >>= 1)
        ss += __shfl_xor_sync(0xFFFFFFFFu, ss, o);
    if (lane == 0) red[wid] = ss;
    __syncthreads();
    float tot = red[lane & 7];
#pragma unroll
    for (int o = 4; o > 0; o >>= 1)
        tot += __shfl_xor_sync(0xFFFFFFFFu, tot, o);
    float scale = rsqrtf(tot / (float)DINNER + 1e-5f);
#pragma unroll
    for (int e = 0; e < 8; e++) {
        int i = e * 256 + t;
        g_yh[(size_t)row * DINNER + i] = __float2half_rn(vals[e] * scale * norm_w[i]);
    }
}

// ---------------- host ------------------------------------------------------
extern "C" void kernel_launch(void* const* d_in, const int* in_sizes, int n_in,
                              void* d_out, int out_size)
{
    const float* u          = (const float*)d_in[0];
    const float* in_proj_w  = (const float*)d_in[1];
    const float* conv_w     = (const float*)d_in[2];
    const float* conv_b     = (const float*)d_in[3];
    const float* init_states= (const float*)d_in[4];
    const float* dt_bias    = (const float*)d_in[5];
    const float* A_log      = (const float*)d_in[6];
    const float* Dp         = (const float*)d_in[7];
    const float* norm_w     = (const float*)d_in[8];
    const float* out_proj_w = (const float*)d_in[9];
    float* out = (float*)d_out;

    cudaFuncSetAttribute((const void*)mma_gemm<0, 2>,
                         cudaFuncAttributeMaxDynamicSharedMemorySize, GSMEM);
    cudaFuncSetAttribute((const void*)mma_gemm<1, 1>,
                         cudaFuncAttributeMaxDynamicSharedMemorySize, GSMEM);
    cudaFuncSetAttribute(chunk_kernel,
                         cudaFuncAttributeMaxDynamicSharedMemorySize, CHUNK_DSMEM);

    __half *p_uh, *p_wih, *p_wil, *p_woh;
    cudaGetSymbolAddress((void**)&p_uh,  g_uh);
    cudaGetSymbolAddress((void**)&p_wih, g_wih);
    cudaGetSymbolAddress((void**)&p_wil, g_wil);
    cudaGetSymbolAddress((void**)&p_woh, g_woh);

    // 0) fp16 preps
    {
        int n4u = NROWS * DMODEL / 4;
        cvt_kernel<<<(n4u + 255) / 256, 256>>>(u, p_uh, n4u);
        int n4wi = DINPROJ * DMODEL / 4;
        split_kernel<<<(n4wi + 255) / 256, 256>>>(in_proj_w, p_wih, p_wil, n4wi);
        int n4wo = DMODEL * DINNER / 4;
        cvt_kernel<<<(n4wo + 255) / 256, 256>>>(out_proj_w, p_woh, n4wo);
    }
    // 1) in_proj GEMM (fp16 2-term) with scatter epilogue
    {
        dim3 grid((DINPROJ + 127) / 128, NROWS / 128);
        mma_gemm<0, 2><<<grid, 256, GSMEM>>>(p_uh, p_wih, p_wil,
                                             nullptr, DINPROJ, DMODEL, dt_bias);
    }
    // 2) causal depthwise conv + silu (4 rows/thread)
    {
        size_t n = (size_t)(NROWS / 4) * (CONVDIM / 4);
        conv_kernel<<<(unsigned)((n + 255) / 256), 256>>>(conv_w, conv_b);
    }
    // 2b) CBT = C @ B^T per (b,chunk)
    cbt_kernel<<<NB * NCHUNK, 256>>>();
    // 3) intra-chunk: Y_diag + chunk states (tensor core) + cumsum
    chunk_kernel<<<NB * NCHUNK * NHEADS, 256, CHUNK_DSMEM>>>(A_log);
    // 4) inter-chunk recurrence (elementwise-parallel)
    recur_kernel<<<(NB * NHEADS * 4096) / 256, 256>>>(init_states);
    // 5) Y_off (tensor core) + skip term
    yoff_kernel<<<NB * NCHUNK * NHEADS, 256>>>(Dp);
    // 6) gate + RMSNorm -> fp16 hi
    norm_kernel<<<NROWS, 256>>>(norm_w);
    // 7) out_proj GEMM (fp16 1-term)
    {
        dim3 grid(DMODEL / 128, NROWS / 128);
        mma_gemm<1, 1><<<grid, 256, GSMEM>>>(nullptr, p_woh, nullptr,
                                             out, DMODEL, DINNER, nullptr);
    }
}

// round 16
// speedup vs baseline: 1.3964x; 1.3964x over previous
#include <cuda_runtime.h>
#include <cuda_fp16.h>
#include <cstdint>

#define NB 4
#define NL 4096
#define DMODEL 1024
#define DINNER 2048
#define NHEADS 32
#define HEADDIM 64
#define DSTATE 64
#define NCHUNK 64
#define CHUNKL 64
#define CONVDIM 2176
#define DINPROJ 4256
#define NROWS (NB*NL)

// ---------------- scratch (device globals; no allocations allowed) ----------
__device__ __align__(16) float g_z[(size_t)NROWS * DINNER];
__device__ __align__(16) float g_xraw[(size_t)NROWS * CONVDIM];
__device__ __align__(16) float g_xbc[(size_t)NROWS * CONVDIM];
__device__ __align__(16) float g_dt[(size_t)NROWS * NHEADS];
__device__ __align__(16) float g_y[(size_t)NROWS * DINNER];
__device__ __align__(16) float g_states[(size_t)NB * NCHUNK * NHEADS * HEADDIM * DSTATE];
__device__ __align__(16) float g_cumsum[(size_t)NB * NHEADS * NCHUNK * CHUNKL];
__device__ __align__(16) float g_cbt[(size_t)NB * NCHUNK * CHUNKL * CHUNKL];

// fp16 operands
__device__ __align__(16) __half g_uh[(size_t)NROWS * DMODEL];
__device__ __align__(16) __half g_wih[(size_t)DINPROJ * DMODEL];
__device__ __align__(16) __half g_wil[(size_t)DINPROJ * DMODEL];
__device__ __align__(16) __half g_woh[(size_t)DMODEL * DINNER];
__device__ __align__(16) __half g_yh[(size_t)NROWS * DINNER];

__device__ __forceinline__ float softplusf(float x) {
    return (x > 20.f) ? x : log1pf(__expf(x));
}
__device__ __forceinline__ float siluf(float x) {
    return __fdividef(x, 1.f + __expf(-x));
}
__device__ __forceinline__ void splith(float v, __half& h, __half& l) {
    h = __float2half_rn(v);
    l = __float2half_rn(v - __half2float(h));
}
__device__ __forceinline__ uint32_t smem_u32(const void* p) {
    uint32_t a;
    asm("{ .reg .u64 t; cvta.to.shared.u64 t, %1; cvt.u32.u64 %0, t; }" : "=r"(a) : "l"(p));
    return a;
}
__device__ __forceinline__ void cpasync16(uint32_t dst, const void* src, uint32_t srcsz) {
    asm volatile("cp.async.cg.shared.global [%0], [%1], 16, %2;"
                 :: "r"(dst), "l"(src), "r"(srcsz) : "memory");
}
#define CP_COMMIT() asm volatile("cp.async.commit_group;" ::: "memory")

__device__ __forceinline__ void ldmat4(uint32_t* r, uint32_t addr) {
    asm volatile("ldmatrix.sync.aligned.m8n8.x4.shared.b16 {%0,%1,%2,%3}, [%4];"
                 : "=r"(r[0]), "=r"(r[1]), "=r"(r[2]), "=r"(r[3]) : "r"(addr));
}
#define MMA_F16(d, a, b) \
    asm volatile("mma.sync.aligned.m16n8k16.row.col.f32.f16.f16.f32 " \
                 "{%0,%1,%2,%3}, {%4,%5,%6,%7}, {%8,%9}, {%0,%1,%2,%3};" \
                 : "+f"((d)[0]), "+f"((d)[1]), "+f"((d)[2]), "+f"((d)[3]) \
                 : "r"((a)[0]), "r"((a)[1]), "r"((a)[2]), "r"((a)[3]), \
                   "r"((b)[0]), "r"((b)[1]))

// ---------------- fp32 -> fp16 conversion preps -----------------------------
__global__ void __launch_bounds__(256) cvt_kernel(
    const float* __restrict__ src, __half* __restrict__ dst, int n4)
{
    int idx = blockIdx.x * 256 + threadIdx.x;
    if (idx >= n4) return;
    float4 v = ((const float4*)src)[idx];
    __half h[4] = {__float2half_rn(v.x), __float2half_rn(v.y),
                   __float2half_rn(v.z), __float2half_rn(v.w)};
    ((uint2*)dst)[idx] = *(uint2*)h;
}
__global__ void __launch_bounds__(256) split_kernel(
    const float* __restrict__ src, __half* __restrict__ hi,
    __half* __restrict__ lo, int n4)
{
    int idx = blockIdx.x * 256 + threadIdx.x;
    if (idx >= n4) return;
    float4 v = ((const float4*)src)[idx];
    __half h[4], l[4];
    splith(v.x, h[0], l[0]); splith(v.y, h[1], l[1]);
    splith(v.z, h[2], l[2]); splith(v.w, h[3], l[3]);
    ((uint2*)hi)[idx] = *(uint2*)h;
    ((uint2*)lo)[idx] = *(uint2*)l;
}

// ========== fp16 mma.sync GEMM: C = A @ W^T ==========
// TERMS=2: Ah·Wh + Ah·Wl, 3 tiles/stage, NSTAGE=2.
// TERMS=1: Ah·Wh, 2 tiles/stage, NSTAGE=3 (deeper pipeline, same smem).
#define GST 72
#define GROWB (GST * 2)
#define GTILE (128 * GST * 2)
#define GSMEM (6 * GTILE)            // 110592 B both configs
template <int MODE, int TERMS, int NSTAGE>
__global__ void __launch_bounds__(256) mma_gemm(
    const __half* __restrict__ Ap, const __half* __restrict__ Whi,
    const __half* __restrict__ Wlo,
    float* __restrict__ Cp, int N_, int K_, const float* __restrict__ dt_bias)
{
    constexpr int STAGEB = (TERMS == 2 ? 3 : 2) * GTILE;
    extern __shared__ char smem[];
    const uint32_t sbase = smem_u32(smem);
    const int tid = threadIdx.x;
    const int row0 = blockIdx.y * 128;
    const int col0 = blockIdx.x * 128;
    const __half* A = (MODE == 0) ? Ap : g_yh;

    const int wid = tid >> 5, lane = tid & 31;
    const int wm = wid >> 2, wn = wid & 3;

    float acc[4][4][4];
#pragma unroll
    for (int i = 0; i < 4; i++)
#pragma unroll
        for (int j = 0; j < 4; j++)
#pragma unroll
            for (int q = 0; q < 4; q++) acc[i][j][q] = 0.f;

    const int iters = K_ >> 6;

    auto load_stage = [&](int st, int buf) {
        const int k0 = st << 6;
        const uint32_t sb = sbase + buf * STAGEB;
#pragma unroll
        for (int p = 0; p < 4; p++) {
            int chunk = tid + p * 256;
            int row = chunk >> 3, c8 = chunk & 7;
            uint32_t doff = (uint32_t)(row * GROWB + c8 * 16);
            size_t aoff = (size_t)(row0 + row) * K_ + k0 + c8 * 8;
            cpasync16(sb + doff, A + aoff, 16u);
            int wr = col0 + row;
            uint32_t wsz = (wr < N_) ? 16u : 0u;
            size_t woff = (size_t)wr * K_ + k0 + c8 * 8;
            cpasync16(sb + GTILE + doff, Whi + woff, wsz);
            if (TERMS == 2)
                cpasync16(sb + 2 * GTILE + doff, Wlo + woff, wsz);
        }
        CP_COMMIT();
    };

#pragma unroll
    for (int s = 0; s < NSTAGE; s++) load_stage(s, s);

    const uint32_t aoffb = (uint32_t)((lane & 15) * GROWB + ((lane >> 4) & 1) * 16);
    const uint32_t boffb = (uint32_t)(((lane & 7) + ((lane >> 4) << 3)) * GROWB + ((lane >> 3) & 1) * 16);

    for (int it = 0; it < iters; it++) {
        asm volatile("cp.async.wait_group %0;" :: "n"(NSTAGE - 1) : "memory");
        __syncthreads();
        const uint32_t sb = sbase + (it % NSTAGE) * STAGEB;
        const uint32_t sAh = sb, sWh = sb + GTILE, sWl = sb + 2 * GTILE;

#pragma unroll
        for (int ks = 0; ks < 4; ks++) {
            uint32_t bh[8], bl[8];
#pragma unroll
            for (int jj = 0; jj < 2; jj++) {
                uint32_t rb = (uint32_t)((wn * 32 + jj * 16) * GROWB) + boffb + ks * 32;
                ldmat4(&bh[jj * 4], sWh + rb);
                if (TERMS == 2) ldmat4(&bl[jj * 4], sWl + rb);
            }
#pragma unroll
            for (int i = 0; i < 4; i++) {
                uint32_t ra = (uint32_t)((wm * 64 + i * 16) * GROWB) + aoffb + ks * 32;
                uint32_t ah[4];
                ldmat4(ah, sAh + ra);
#pragma unroll
                for (int j = 0; j < 4; j++)
                    MMA_F16(acc[i][j], ah, &bh[(j >> 1) * 4 + (j & 1) * 2]);
                if (TERMS == 2) {
#pragma unroll
                    for (int j = 0; j < 4; j++)
                        MMA_F16(acc[i][j], ah, &bl[(j >> 1) * 4 + (j & 1) * 2]);
                }
            }
        }
        __syncthreads();
        if (it + NSTAGE < iters) load_stage(it + NSTAGE, it % NSTAGE);
    }

#pragma unroll
    for (int i = 0; i < 4; i++) {
        const int rb = row0 + wm * 64 + i * 16 + (lane >> 2);
#pragma unroll
        for (int j = 0; j < 4; j++) {
            const int c = col0 + wn * 32 + j * 8 + (lane & 3) * 2;
#pragma unroll
            for (int half = 0; half < 2; half++) {
                const int r = rb + half * 8;
                const float v0 = acc[i][j][half * 2];
                const float v1 = acc[i][j][half * 2 + 1];
                if (MODE == 0) {
                    if (c < DINNER) {
                        *(float2*)&g_z[(size_t)r * DINNER + c] = make_float2(v0, v1);
                    } else if (c < DINNER + CONVDIM) {
                        *(float2*)&g_xraw[(size_t)r * CONVDIM + (c - DINNER)] = make_float2(v0, v1);
                    } else if (c < DINPROJ) {
                        int h = c - (DINNER + CONVDIM);
                        g_dt[(size_t)r * NHEADS + h] = softplusf(v0 + dt_bias[h]);
                        g_dt[(size_t)r * NHEADS + h + 1] = softplusf(v1 + dt_bias[h + 1]);
                    }
                } else {
                    *(float2*)&Cp[(size_t)r * N_ + c] = make_float2(v0, v1);
                }
            }
        }
    }
}

// -------- depthwise conv (k=4, causal) + silu, 4 rows per thread -----------
__global__ void __launch_bounds__(256) conv_kernel(
    const float* __restrict__ conv_w, const float* __restrict__ conv_b)
{
    const int CV4 = CONVDIM / 4;
    size_t idx = (size_t)blockIdx.x * blockDim.x + threadIdx.x;
    if (idx >= (size_t)(NROWS / 4) * CV4) return;
    int chv = (int)(idx % CV4);
    int blg = (int)(idx / CV4);
    int l0 = (blg % (NL / 4)) * 4;
    int b  = blg / (NL / 4);
    int ch = chv * 4;

    float4 x[7];
#pragma unroll
    for (int k = 0; k < 7; k++) {
        int ls = l0 - 3 + k;
        x[k] = (ls >= 0)
            ? *(const float4*)&g_xraw[((size_t)b * NL + ls) * CONVDIM + ch]
            : make_float4(0.f, 0.f, 0.f, 0.f);
    }
    float w[4][4], bia[4];
#pragma unroll
    for (int i = 0; i < 4; i++) {
        bia[i] = conv_b[ch + i];
#pragma unroll
        for (int k = 0; k < 4; k++) w[i][k] = conv_w[(ch + i) * 4 + k];
    }
#pragma unroll
    for (int r = 0; r < 4; r++) {
        float a0 = bia[0], a1 = bia[1], a2 = bia[2], a3 = bia[3];
#pragma unroll
        for (int k = 0; k < 4; k++) {
            const float4 xv = x[r + k];
            a0 = fmaf(xv.x, w[0][k], a0);
            a1 = fmaf(xv.y, w[1][k], a1);
            a2 = fmaf(xv.z, w[2][k], a2);
            a3 = fmaf(xv.w, w[3][k], a3);
        }
        float4 o;
        o.x = siluf(a0); o.y = siluf(a1); o.z = siluf(a2); o.w = siluf(a3);
        *(float4*)&g_xbc[((size_t)b * NL + l0 + r) * CONVDIM + ch] = o;
    }
}

// ---------------- CBT = C @ B^T per (b,chunk), shared across heads ----------
__global__ void __launch_bounds__(256) cbt_kernel()
{
    __shared__ float Bs[64 * 65];
    __shared__ float Cs[64 * 65];
    const int bc = blockIdx.x;
    const int t = threadIdx.x;

    for (int idx = t; idx < 64 * 16; idx += 256) {
        int l = idx >> 4;
        int n4 = (idx & 15) * 4;
        size_t base = ((size_t)bc * CHUNKL + l) * CONVDIM;
        float4 bv = *(const float4*)&g_xbc[base + DINNER + n4];
        float4 cv = *(const float4*)&g_xbc[base + DINNER + 64 + n4];
        Bs[l * 65 + n4 + 0] = bv.x; Bs[l * 65 + n4 + 1] = bv.y;
        Bs[l * 65 + n4 + 2] = bv.z; Bs[l * 65 + n4 + 3] = bv.w;
        Cs[l * 65 + n4 + 0] = cv.x; Cs[l * 65 + n4 + 1] = cv.y;
        Cs[l * 65 + n4 + 2] = cv.z; Cs[l * 65 + n4 + 3] = cv.w;
    }
    __syncthreads();

    const int r0 = (t >> 4) * 4;
    const int c0 = (t & 15) * 4;
    float ga[4][4];
#pragma unroll
    for (int i = 0; i < 4; i++)
#pragma unroll
        for (int j = 0; j < 4; j++) ga[i][j] = 0.f;
    for (int n = 0; n < 64; n++) {
        float cr[4], br[4];
#pragma unroll
        for (int i = 0; i < 4; i++) cr[i] = Cs[(r0 + i) * 65 + n];
#pragma unroll
        for (int j = 0; j < 4; j++) br[j] = Bs[(c0 + j) * 65 + n];
#pragma unroll
        for (int i = 0; i < 4; i++)
#pragma unroll
            for (int j = 0; j < 4; j++) ga[i][j] = fmaf(cr[i], br[j], ga[i][j]);
    }
    float* dst = g_cbt + (size_t)bc * 4096;
#pragma unroll
    for (int i = 0; i < 4; i++)
#pragma unroll
        for (int j = 0; j < 4; j++)
            dst[(r0 + i) * 64 + c0 + j] = ga[i][j];
}

// ======== chunk: tensor-core state + Y_diag (fp16 2-term mma.sync) ==========
// Original (R13) split mapping — known-good.
#define CST 72
#define CROWB (CST * 2)
#define TILE_B (64 * CST * 2)
#define CHUNK_DSMEM (5 * TILE_B + 3 * 64 * 4)
__global__ void __launch_bounds__(256) chunk_kernel(const float* __restrict__ A_log)
{
    extern __shared__ __align__(16) char sm[];
    __half* Gh = (__half*)sm;
    __half* Xh = Gh + 64 * CST;
    __half* Xl = Xh + 64 * CST;
    __half* Bh = Xl + 64 * CST;
    __half* Bl = Bh + 64 * CST;
    float* cum = (float*)(Bl + 64 * CST);
    float* dts = cum + 64;
    float* dec = dts + 64;
    const uint32_t sb = smem_u32(sm);
    const uint32_t sGh = sb, sXh = sGh + TILE_B, sXl = sXh + TILE_B,
                   sBh = sXl + TILE_B, sBl = sBh + TILE_B;

    const int blk = blockIdx.x;
    const int h = blk & (NHEADS - 1);
    const int c = (blk / NHEADS) & (NCHUNK - 1);
    const int b = blk / (NHEADS * NCHUNK);
    const int t = threadIdx.x;
    const int wid = t >> 5, lane = t & 31;

    const float Ah_ = -__expf(A_log[h]);

    if (t < 64) {
        float d = g_dt[((size_t)(b * NL + c * CHUNKL + t)) * NHEADS + h];
        dts[t] = d;
        cum[t] = Ah_ * d;
    }
    __syncthreads();
    if (t == 0) {
        float s = 0.f;
        for (int l = 0; l < 64; l++) { s += cum[l]; cum[l] = s; }
    }
    __syncthreads();
    if (t < 64) {
        dec[t] = __expf(cum[63] - cum[t]);
        g_cumsum[(((size_t)(b * NHEADS + h)) * NCHUNK + c) * CHUNKL + t] = cum[t];
    }
    __syncthreads();

    const float* cbt = g_cbt + ((size_t)(b * NCHUNK + c)) * 4096;
    for (int idx = t; idx < 64 * 16; idx += 256) {
        int l = idx >> 4;
        int q = (idx & 15) * 4;
        size_t base = ((size_t)(b * NL + c * CHUNKL + l)) * CONVDIM;
        float4 bv = *(const float4*)&g_xbc[base + DINNER + q];
        float4 xv = *(const float4*)&g_xbc[base + h * HEADDIM + q];
        float4 gv = *(const float4*)&cbt[l * 64 + q];
        float dtl = dts[l], dl = dec[l], cl = cum[l];
        float xa[4] = {xv.x * dtl, xv.y * dtl, xv.z * dtl, xv.w * dtl};
        float ba[4] = {bv.x * dl, bv.y * dl, bv.z * dl, bv.w * dl};
        float ga[4] = {gv.x, gv.y, gv.z, gv.w};
#pragma unroll
        for (int i = 0; i < 4; i++) {
            __half hh, ll;
            splith(xa[i], hh, ll);
            Xh[(q + i) * CST + l] = hh; Xl[(q + i) * CST + l] = ll;
            splith(ba[i], hh, ll);
            Bh[(q + i) * CST + l] = hh; Bl[(q + i) * CST + l] = ll;
            int s = q + i;
            float gm = (l >= s) ? ga[i] * __expf(cl - cum[s]) : 0.f;
            Gh[l * CST + s] = __float2half_rn(gm);
        }
    }
    __syncthreads();

    const int rows0 = (wid & 3) * 16;
    const uint32_t aoffb = (uint32_t)((lane & 15) * CROWB + ((lane >> 4) & 1) * 16);
    const uint32_t boffb = (uint32_t)(((lane & 7) + ((lane >> 4) << 3)) * CROWB + ((lane >> 3) & 1) * 16);

    const uint32_t sA_h = (wid < 4) ? sXh : sGh;
    const uint32_t sB_h = (wid < 4) ? sBh : sXh;
    const uint32_t sB_l = (wid < 4) ? sBl : sXl;

    float acc[8][4];
#pragma unroll
    for (int j = 0; j < 8; j++)
#pragma unroll
        for (int q = 0; q < 4; q++) acc[j][q] = 0.f;

#pragma unroll
    for (int kt = 0; kt < 4; kt++) {
        uint32_t ah[4];
        ldmat4(ah, sA_h + rows0 * CROWB + aoffb + kt * 32);
#pragma unroll
        for (int jj = 0; jj < 4; jj++) {
            uint32_t bh[4], bl4[4];
            uint32_t rb = (uint32_t)(jj * 16 * CROWB) + boffb + kt * 32;
            ldmat4(bh, sB_h + rb);
            ldmat4(bl4, sB_l + rb);
            MMA_F16(acc[jj * 2],     ah, &bh[0]);
            MMA_F16(acc[jj * 2 + 1], ah, &bh[2]);
            MMA_F16(acc[jj * 2],     ah, &bl4[0]);
            MMA_F16(acc[jj * 2 + 1], ah, &bl4[2]);
        }
    }

    if (wid < 4) {
        size_t sbout = (size_t)blk * (HEADDIM * DSTATE);
#pragma unroll
        for (int j = 0; j < 8; j++) {
            int n = j * 8 + (lane & 3) * 2;
            int p = rows0 + (lane >> 2);
            *(float2*)&g_states[sbout + (size_t)p * DSTATE + n] = make_float2(acc[j][0], acc[j][1]);
            *(float2*)&g_states[sbout + (size_t)(p + 8) * DSTATE + n] = make_float2(acc[j][2], acc[j][3]);
        }
    } else {
#pragma unroll
        for (int j = 0; j < 8; j++) {
            int p = j * 8 + (lane & 3) * 2;
#pragma unroll
            for (int half = 0; half < 2; half++) {
                int l = rows0 + (lane >> 2) + half * 8;
                int lg = c * CHUNKL + l;
                *(float2*)&g_y[((size_t)(b * NL + lg)) * DINNER + h * HEADDIM + p] =
                    make_float2(acc[j][half * 2], acc[j][half * 2 + 1]);
            }
        }
    }
}

// ---------------- inter-chunk recurrence: one thread per element ------------
__global__ void __launch_bounds__(256) recur_kernel(const float* __restrict__ init_states)
{
    __shared__ float dcs[64];
    const int t = threadIdx.x;
    const int gid = blockIdx.x * 256 + t;
    const int e = gid & 4095;
    const int bh = gid >> 12;
    const int b = bh >> 5, h = bh & 31;

    if (t < 64)
        dcs[t] = __expf(g_cumsum[((size_t)bh * NCHUNK + t) * CHUNKL + 63]);
    __syncthreads();

    float S = init_states[(size_t)h * 4096 + e];
    float* sp0 = g_states + ((((size_t)b * NCHUNK) * NHEADS + h) << 12) + e;
    const size_t cstride = (size_t)NHEADS << 12;

    float cs = sp0[0];
    for (int c = 0; c < NCHUNK; c++) {
        float* sp = sp0 + (size_t)c * cstride;
        float csn = (c < NCHUNK - 1) ? sp[cstride] : 0.f;
        *sp = S;
        S = fmaf(S, dcs[c], cs);
        cs = csn;
    }
}

// ========= Y_off (tensor-core fp16 2-term): Y += es[l]*(C @ S^T) + x*D ======
__global__ void __launch_bounds__(256) yoff_kernel(const float* __restrict__ Dp)
{
    __shared__ __align__(16) char sm[3 * TILE_B + 64 * 4];
    __half* Ch = (__half*)sm;
    __half* Sh = Ch + 64 * CST;
    __half* Sl = Sh + 64 * CST;
    float* es = (float*)(Sl + 64 * CST);
    const uint32_t sb = smem_u32(sm);
    const uint32_t sCh = sb, sSh = sCh + TILE_B, sSl = sSh + TILE_B;

    const int blk = blockIdx.x;
    const int h = blk & (NHEADS - 1);
    const int c = (blk / NHEADS) & (NCHUNK - 1);
    const int b = blk / (NHEADS * NCHUNK);
    const int t = threadIdx.x;
    const int wid = t >> 5, lane = t & 31;
    const float Dh = Dp[h];

    if (t < 64)
        es[t] = __expf(g_cumsum[(((size_t)(b * NHEADS + h)) * NCHUNK + c) * CHUNKL + t]);

    for (int idx = t; idx < 64 * 16; idx += 256) {
        int r = idx >> 4;
        int q = (idx & 15) * 4;
        size_t base = ((size_t)(b * NL + c * CHUNKL + r)) * CONVDIM;
        float4 cv = *(const float4*)&g_xbc[base + DINNER + 64 + q];
        float4 sv = *(const float4*)&g_states[(size_t)blk * 4096 + r * 64 + q];
        float ca[4] = {cv.x, cv.y, cv.z, cv.w};
        float sa[4] = {sv.x, sv.y, sv.z, sv.w};
#pragma unroll
        for (int i = 0; i < 4; i++) {
            Ch[r * CST + q + i] = __float2half_rn(ca[i]);
            __half hh, ll;
            splith(sa[i], hh, ll);
            Sh[r * CST + q + i] = hh; Sl[r * CST + q + i] = ll;
        }
    }
    __syncthreads();

    const int lrow0 = (wid & 3) * 16;
    const int p0 = (wid >> 2) * 32;
    const uint32_t aoffb = (uint32_t)((lane & 15) * CROWB + ((lane >> 4) & 1) * 16);
    const uint32_t boffb = (uint32_t)(((lane & 7) + ((lane >> 4) << 3)) * CROWB + ((lane >> 3) & 1) * 16);

    float acc[4][4];
#pragma unroll
    for (int j = 0; j < 4; j++)
#pragma unroll
        for (int q = 0; q < 4; q++) acc[j][q] = 0.f;

#pragma unroll
    for (int kt = 0; kt < 4; kt++) {
        uint32_t ah[4];
        ldmat4(ah, sCh + lrow0 * CROWB + aoffb + kt * 32);
#pragma unroll
        for (int jj = 0; jj < 2; jj++) {
            uint32_t bh[4], bl4[4];
            uint32_t rb = (uint32_t)((p0 + jj * 16) * CROWB) + boffb + kt * 32;
            ldmat4(bh, sSh + rb);
            ldmat4(bl4, sSl + rb);
            MMA_F16(acc[jj * 2],     ah, &bh[0]);
            MMA_F16(acc[jj * 2 + 1], ah, &bh[2]);
            MMA_F16(acc[jj * 2],     ah, &bl4[0]);
            MMA_F16(acc[jj * 2 + 1], ah, &bl4[2]);
        }
    }

#pragma unroll
    for (int j = 0; j < 4; j++) {
        int p = p0 + j * 8 + (lane & 3) * 2;
#pragma unroll
        for (int half = 0; half < 2; half++) {
            int l = lrow0 + (lane >> 2) + half * 8;
            int lg = c * CHUNKL + l;
            float e = es[l];
            size_t yi = ((size_t)(b * NL + lg)) * DINNER + h * HEADDIM + p;
            float2 yv = *(float2*)&g_y[yi];
            float2 xv = *(float2*)&g_xbc[((size_t)(b * NL + lg)) * CONVDIM + h * HEADDIM + p];
            yv.x = yv.x + e * acc[j][half * 2]     + xv.x * Dh;
            yv.y = yv.y + e * acc[j][half * 2 + 1] + xv.y * Dh;
            *(float2*)&g_y[yi] = yv;
        }
    }
}

// ------- gating (silu(z)) + RMSNorm, emits fp16 hi for out_proj -------------
__global__ void __launch_bounds__(256) norm_kernel(const float* __restrict__ norm_w)
{
    __shared__ float red[8];
    const int row = blockIdx.x;
    const int t = threadIdx.x;
    const int lane = t & 31, wid = t >> 5;
    const float* yr = g_y + (size_t)row * DINNER;
    const float* zr = g_z + (size_t)row * DINNER;

    float vals[8];
    float ss = 0.f;
#pragma unroll
    for (int e = 0; e < 8; e++) {
        int i = e * 256 + t;
        float v = yr[i] * siluf(zr[i]);
        vals[e] = v;
        ss = fmaf(v, v, ss);
    }
#pragma unroll
    for (int o = 16; o > 0; o >>= 1)
        ss += __shfl_xor_sync(0xFFFFFFFFu, ss, o);
    if (lane == 0) red[wid] = ss;
    __syncthreads();
    float tot = red[lane & 7];
#pragma unroll
    for (int o = 4; o > 0; o >>= 1)
        tot += __shfl_xor_sync(0xFFFFFFFFu, tot, o);
    float scale = rsqrtf(tot / (float)DINNER + 1e-5f);
#pragma unroll
    for (int e = 0; e < 8; e++) {
        int i = e * 256 + t;
        g_yh[(size_t)row * DINNER + i] = __float2half_rn(vals[e] * scale * norm_w[i]);
    }
}

// ---------------- host ------------------------------------------------------
extern "C" void kernel_launch(void* const* d_in, const int* in_sizes, int n_in,
                              void* d_out, int out_size)
{
    const float* u          = (const float*)d_in[0];
    const float* in_proj_w  = (const float*)d_in[1];
    const float* conv_w     = (const float*)d_in[2];
    const float* conv_b     = (const float*)d_in[3];
    const float* init_states= (const float*)d_in[4];
    const float* dt_bias    = (const float*)d_in[5];
    const float* A_log      = (const float*)d_in[6];
    const float* Dp         = (const float*)d_in[7];
    const float* norm_w     = (const float*)d_in[8];
    const float* out_proj_w = (const float*)d_in[9];
    float* out = (float*)d_out;

    cudaFuncSetAttribute((const void*)mma_gemm<0, 2, 2>,
                         cudaFuncAttributeMaxDynamicSharedMemorySize, GSMEM);
    cudaFuncSetAttribute((const void*)mma_gemm<1, 1, 3>,
                         cudaFuncAttributeMaxDynamicSharedMemorySize, GSMEM);
    cudaFuncSetAttribute(chunk_kernel,
                         cudaFuncAttributeMaxDynamicSharedMemorySize, CHUNK_DSMEM);

    __half *p_uh, *p_wih, *p_wil, *p_woh;
    cudaGetSymbolAddress((void**)&p_uh,  g_uh);
    cudaGetSymbolAddress((void**)&p_wih, g_wih);
    cudaGetSymbolAddress((void**)&p_wil, g_wil);
    cudaGetSymbolAddress((void**)&p_woh, g_woh);

    // 0) fp16 preps
    {
        int n4u = NROWS * DMODEL / 4;
        cvt_kernel<<<(n4u + 255) / 256, 256>>>(u, p_uh, n4u);
        int n4wi = DINPROJ * DMODEL / 4;
        split_kernel<<<(n4wi + 255) / 256, 256>>>(in_proj_w, p_wih, p_wil, n4wi);
        int n4wo = DMODEL * DINNER / 4;
        cvt_kernel<<<(n4wo + 255) / 256, 256>>>(out_proj_w, p_woh, n4wo);
    }
    // 1) in_proj GEMM (fp16 2-term, 2-stage) with scatter epilogue
    {
        dim3 grid((DINPROJ + 127) / 128, NROWS / 128);
        mma_gemm<0, 2, 2><<<grid, 256, GSMEM>>>(p_uh, p_wih, p_wil,
                                                nullptr, DINPROJ, DMODEL, dt_bias);
    }
    // 2) causal depthwise conv + silu (4 rows/thread)
    {
        size_t n = (size_t)(NROWS / 4) * (CONVDIM / 4);
        conv_kernel<<<(unsigned)((n + 255) / 256), 256>>>(conv_w, conv_b);
    }
    // 2b) CBT = C @ B^T per (b,chunk)
    cbt_kernel<<<NB * NCHUNK, 256>>>();
    // 3) intra-chunk: Y_diag + chunk states (tensor core) + cumsum
    chunk_kernel<<<NB * NCHUNK * NHEADS, 256, CHUNK_DSMEM>>>(A_log);
    // 4) inter-chunk recurrence (elementwise-parallel)
    recur_kernel<<<(NB * NHEADS * 4096) / 256, 256>>>(init_states);
    // 5) Y_off (tensor core) + skip term
    yoff_kernel<<<NB * NCHUNK * NHEADS, 256>>>(Dp);
    // 6) gate + RMSNorm -> fp16 hi
    norm_kernel<<<NROWS, 256>>>(norm_w);
    // 7) out_proj GEMM (fp16 1-term, 3-stage pipeline)
    {
        dim3 grid(DMODEL / 128, NROWS / 128);
        mma_gemm<1, 1, 3><<<grid, 256, GSMEM>>>(nullptr, p_woh, nullptr,
                                                out, DMODEL, DINNER, nullptr);
    }
}